// round 2
// baseline (speedup 1.0000x reference)
#include <cuda_runtime.h>
#include <cuda_fp16.h>
#include <math.h>

#define NN 100000
#define NE 3200000
#define FIN 32
#define HD 64
#define NL 4
#define NA 6158
#define NG 64

// ---------------- scratch (device globals; no allocation allowed) -------------
__device__ int   d_flag;              // 1 if inputs are int64, 0 if int32
__device__ int   d_src[NE];
__device__ int   d_dst[NE];
__device__ int   d_batch32[NN];
__device__ int   d_deg[NN];
__device__ int   d_rowptr[NN + 1];
__device__ int   d_cursor[NN];
__device__ int   d_csr[NE];
__device__ float d_invdeg[NN];
__device__ float d_h0[NN * HD];
__device__ float d_h1[NN * HD];
__device__ __half2 d_hh[NN * 32];     // fp16 copy of current h for gathers
__device__ float d_agg[NN * HD];
__device__ float d_gsum[NG * HD];
__device__ int   d_gcnt[NG];
__device__ int   d_part[256];

// ---------------- f32x2 packed-FMA helpers -------------------------------------
__device__ __forceinline__ unsigned long long pack2(float x) {
    unsigned long long r;
    asm("mov.b64 %0, {%1, %1};" : "=l"(r) : "f"(x));
    return r;
}
__device__ __forceinline__ void ffma2(unsigned long long& d,
                                      unsigned long long a,
                                      unsigned long long b) {
    asm("fma.rn.f32x2 %0, %1, %2, %0;" : "+l"(d) : "l"(a), "l"(b));
}
__device__ __forceinline__ void unpack2(unsigned long long v, float& lo, float& hi) {
    asm("mov.b64 {%0, %1}, %2;" : "=f"(lo), "=f"(hi) : "l"(v));
}

// ---------------- dtype detection + conversion --------------------------------
__global__ void k_detect(const void* edge) {
    const unsigned int* w = (const unsigned int*)edge;
    int zeros = 0;
    for (int i = 0; i < 128; i++) if (w[2 * i + 1] == 0u) zeros++;
    d_flag = (zeros >= 120) ? 1 : 0;
}

// converts edges AND accumulates in-degree for dst (fused, saves a 12.8MB pass)
__global__ void k_convert_edges(const void* edge) {
    int i = blockIdx.x * blockDim.x + threadIdx.x;
    if (i >= 2 * NE) return;
    int v;
    if (d_flag) v = (int)((const long long*)edge)[i];
    else        v = ((const int*)edge)[i];
    if (i < NE) d_src[i] = v;
    else        { d_dst[i - NE] = v; atomicAdd(&d_deg[v], 1); }
}

// zero degree + graph accumulators, convert batch ids (runs BEFORE convert)
__global__ void k_setup(const void* batch) {
    int i = blockIdx.x * blockDim.x + threadIdx.x;
    if (i < NN) {
        d_deg[i] = 0;
        int b;
        if (d_flag) b = (int)((const long long*)batch)[i];
        else        b = ((const int*)batch)[i];
        d_batch32[i] = b;
    }
    if (i < NG) d_gcnt[i] = 0;
    if (i < NG * HD) d_gsum[i] = 0.f;
}

__global__ void k_invdeg() {
    int n = blockIdx.x * blockDim.x + threadIdx.x;
    if (n >= NN) return;
    d_invdeg[n] = 1.0f / fmaxf((float)d_deg[n], 1.0f);
}

// ---------------- CSR build (scan over degrees) --------------------------------
__global__ void k_scan_a() {
    __shared__ int ts[256];
    int b = blockIdx.x, t = threadIdx.x;
    int base = b * 1024 + t * 4;
    int v[4];
    int s = 0;
#pragma unroll
    for (int j = 0; j < 4; j++) {
        int idx = base + j;
        v[j] = (idx < NN) ? d_deg[idx] : 0;
        s += v[j];
    }
    ts[t] = s;
    __syncthreads();
    for (int off = 1; off < 256; off <<= 1) {
        int x = (t >= off) ? ts[t - off] : 0;
        __syncthreads();
        ts[t] += x;
        __syncthreads();
    }
    int run = ts[t] - s;
#pragma unroll
    for (int j = 0; j < 4; j++) {
        int idx = base + j;
        if (idx < NN) d_rowptr[idx] = run;
        run += v[j];
    }
    if (t == 255) d_part[b] = ts[255];
}

__global__ void k_scan_b() {
    __shared__ int ps[128];
    int t = threadIdx.x;
    int orig = (t < 98) ? d_part[t] : 0;
    ps[t] = orig;
    __syncthreads();
    for (int off = 1; off < 128; off <<= 1) {
        int x = (t >= off) ? ps[t - off] : 0;
        __syncthreads();
        ps[t] += x;
        __syncthreads();
    }
    d_part[t] = ps[t] - orig;
    if (t == 0) d_rowptr[NN] = NE;
}

__global__ void k_scan_c() {
    int i = blockIdx.x * blockDim.x + threadIdx.x;
    if (i >= NN) return;
    int r = d_rowptr[i] + d_part[i >> 10];
    d_rowptr[i] = r;
    d_cursor[i] = r;
}

__global__ void k_scatter() {
    int e = blockIdx.x * blockDim.x + threadIdx.x;
    if (e >= NE) return;
    int dd = d_dst[e];
    int pos = atomicAdd(&d_cursor[dd], 1);
    d_csr[pos] = d_src[e];
}

// ---------------- encoder: h0 = relu(x @ W_enc^T + b_enc), writes fp32 + fp16 --
__global__ void k_encoder(const float* __restrict__ x,
                          const float* __restrict__ Wenc,
                          const float* __restrict__ benc) {
    __shared__ float Ws[FIN * HD];  // transposed: Ws[k*HD + j]
    __shared__ float bs[HD];
    int t = threadIdx.x;
    for (int i = t; i < HD * FIN; i += blockDim.x) {
        int j = i / FIN, k = i % FIN;
        Ws[k * HD + j] = Wenc[i];
    }
    if (t < HD) bs[t] = benc[t];
    __syncthreads();
    int idx = blockIdx.x * blockDim.x + t;
    if (idx >= NN * 32) return;
    int n = idx >> 5, j2 = idx & 31;
    int j = 2 * j2;
    const float* xr = x + n * FIN;
    float a0 = bs[j], a1 = bs[j + 1];
#pragma unroll
    for (int k = 0; k < FIN; k += 4) {
        float4 xv = *(const float4*)(xr + k);
        float2 w0 = *(const float2*)(&Ws[k * HD + j]);
        float2 w1 = *(const float2*)(&Ws[(k + 1) * HD + j]);
        float2 w2 = *(const float2*)(&Ws[(k + 2) * HD + j]);
        float2 w3 = *(const float2*)(&Ws[(k + 3) * HD + j]);
        a0 += xv.x * w0.x + xv.y * w1.x + xv.z * w2.x + xv.w * w3.x;
        a1 += xv.x * w0.y + xv.y * w1.y + xv.z * w2.y + xv.w * w3.y;
    }
    a0 = fmaxf(a0, 0.f);
    a1 = fmaxf(a1, 0.f);
    ((float2*)d_h0)[idx] = make_float2(a0, a1);
    d_hh[idx] = __floats2half2_rn(a0, a1);
}

// ---------------- aggregation: agg[n] = mean_{e: dst=n} h_fp16[src[e]] ---------
__global__ void k_aggregate() {
    int w = (blockIdx.x * blockDim.x + threadIdx.x) >> 5;
    if (w >= NN) return;
    int lane = threadIdx.x & 31;
    int beg = d_rowptr[w], end = d_rowptr[w + 1];
    float ax = 0.f, ay = 0.f;
    int i = beg;
    for (; i + 4 <= end; i += 4) {
        int s0 = d_csr[i], s1 = d_csr[i + 1], s2 = d_csr[i + 2], s3 = d_csr[i + 3];
        float2 v0 = __half22float2(d_hh[s0 * 32 + lane]);
        float2 v1 = __half22float2(d_hh[s1 * 32 + lane]);
        float2 v2 = __half22float2(d_hh[s2 * 32 + lane]);
        float2 v3 = __half22float2(d_hh[s3 * 32 + lane]);
        ax += v0.x + v1.x + v2.x + v3.x;
        ay += v0.y + v1.y + v2.y + v3.y;
    }
    for (; i < end; i++) {
        float2 v = __half22float2(d_hh[d_csr[i] * 32 + lane]);
        ax += v.x; ay += v.y;
    }
    float id = d_invdeg[w];
    ((float2*)d_agg)[w * 32 + lane] = make_float2(ax * id, ay * id);
}

// ---------------- layer: h_out = relu(agg@Wl^T + bl + h@Wr^T) + h --------------
// f32x2 packed FMAs; W transposed in smem with pad-68 rows (16B aligned).
#define WPAD 68
__global__ void __launch_bounds__(128)
k_layer(int sel,
        const float* __restrict__ Wl, const float* __restrict__ bl,
        const float* __restrict__ Wr) {
    const float* h    = sel ? d_h1 : d_h0;
    float*       hout = sel ? d_h0 : d_h1;
    __shared__ float Wls[HD * WPAD];  // Wls[k*WPAD + j] = Wl[j][k]
    __shared__ float Wrs[HD * WPAD];
    __shared__ float bls[HD];
    int t = threadIdx.x;
    for (int i = t; i < HD * HD; i += 128) {
        int j = i >> 6, k = i & 63;           // coalesced global read
        Wls[k * WPAD + j] = Wl[i];
        Wrs[k * WPAD + j] = Wr[i];
    }
    if (t < HD) bls[t] = bl[t];
    __syncthreads();
    int n = blockIdx.x * 128 + t;
    if (n >= NN) return;

    unsigned long long acc2[32];
#pragma unroll
    for (int j2 = 0; j2 < 32; j2++)
        acc2[j2] = ((const unsigned long long*)bls)[j2];  // bias pre-packed

    const float4* __restrict__ ar = (const float4*)(d_agg + n * HD);
    const float4* __restrict__ hr = (const float4*)(h + n * HD);
#pragma unroll 1
    for (int k4 = 0; k4 < 16; k4++) {
        float4 a = ar[k4];
        float4 b = hr[k4];
        unsigned long long aa[4] = {pack2(a.x), pack2(a.y), pack2(a.z), pack2(a.w)};
        unsigned long long hh[4] = {pack2(b.x), pack2(b.y), pack2(b.z), pack2(b.w)};
#pragma unroll
        for (int kk = 0; kk < 4; kk++) {
            int k = k4 * 4 + kk;
            const ulonglong2* __restrict__ wl = (const ulonglong2*)&Wls[k * WPAD];
            const ulonglong2* __restrict__ wr = (const ulonglong2*)&Wrs[k * WPAD];
#pragma unroll
            for (int j4 = 0; j4 < 16; j4++) {
                ulonglong2 wlv = wl[j4];
                ulonglong2 wrv = wr[j4];
                ffma2(acc2[2 * j4 + 0], aa[kk], wlv.x);
                ffma2(acc2[2 * j4 + 1], aa[kk], wlv.y);
                ffma2(acc2[2 * j4 + 0], hh[kk], wrv.x);
                ffma2(acc2[2 * j4 + 1], hh[kk], wrv.y);
            }
        }
    }

    const float2* __restrict__ hres = (const float2*)(h + n * HD);
#pragma unroll
    for (int j2 = 0; j2 < 32; j2++) {
        float lo, hi;
        unpack2(acc2[j2], lo, hi);
        float2 hv = hres[j2];
        float o0 = fmaxf(lo, 0.f) + hv.x;
        float o1 = fmaxf(hi, 0.f) + hv.y;
        ((float2*)hout)[n * 32 + j2] = make_float2(o0, o1);
        d_hh[n * 32 + j2] = __floats2half2_rn(o0, o1);
    }
}

// ---------------- global mean pool ---------------------------------------------
__global__ void k_count() {
    int n = blockIdx.x * blockDim.x + threadIdx.x;
    if (n >= NN) return;
    atomicAdd(&d_gcnt[d_batch32[n]], 1);
}

__global__ void k_pool(int sel) {
    const float* h = sel ? d_h1 : d_h0;
    int t = threadIdx.x;
    int n0 = blockIdx.x * 256;
    if (n0 >= NN) return;
    int nend = n0 + 256; if (nend > NN) nend = NN;
    int cur = d_batch32[n0];
    float acc = 0.f;
    for (int n = n0; n < nend; n++) {
        int g = d_batch32[n];
        if (g != cur) {
            atomicAdd(&d_gsum[cur * HD + t], acc);
            acc = 0.f;
            cur = g;
        }
        acc += h[n * HD + t];
    }
    atomicAdd(&d_gsum[cur * HD + t], acc);
}

// ---------------- heads --------------------------------------------------------
__global__ void __launch_bounds__(128)
k_policy(const float* __restrict__ Wp, const float* __restrict__ bp,
         float* __restrict__ out) {
    __shared__ float repr[NG * HD];
    int t = threadIdx.x;
    for (int i = t; i < NG * HD; i += 128) {
        int g = i >> 6;
        repr[i] = d_gsum[i] / fmaxf((float)d_gcnt[g], 1.f);
    }
    __syncthreads();
    int a = blockIdx.x * 128 + t;
    if (a >= NA) return;
    float acc[NG];
#pragma unroll
    for (int g = 0; g < NG; g++) acc[g] = 0.f;
    const float4* __restrict__ wr = (const float4*)(Wp + a * HD);
#pragma unroll 2
    for (int k4 = 0; k4 < 16; k4++) {
        float4 w = wr[k4];
#pragma unroll
        for (int g = 0; g < NG; g++) {
            float4 r = *(const float4*)(&repr[g * HD + k4 * 4]);
            acc[g] += w.x * r.x + w.y * r.y + w.z * r.z + w.w * r.w;
        }
    }
    float bias = bp[a];
#pragma unroll
    for (int g = 0; g < NG; g++) out[g * NA + a] = acc[g] + bias;
}

__global__ void k_value(const float* __restrict__ Wv,
                        const float* __restrict__ bv,
                        float* __restrict__ out) {
    int g = threadIdx.x;
    if (g >= NG) return;
    float inv = 1.f / fmaxf((float)d_gcnt[g], 1.f);
    float acc = 0.f;
#pragma unroll
    for (int k = 0; k < HD; k++) acc += d_gsum[g * HD + k] * Wv[k];
    out[NG * NA + g] = tanhf(acc * inv + bv[0]);
}

// ---------------- launcher -----------------------------------------------------
extern "C" void kernel_launch(void* const* d_in, const int* in_sizes, int n_in,
                              void* d_out, int out_size) {
    const float* x     = (const float*)d_in[0];
    const void*  edge  = d_in[1];
    const void*  batch = d_in[2];
    const float* Wenc  = (const float*)d_in[3];
    const float* benc  = (const float*)d_in[4];
    const float* Wl    = (const float*)d_in[5];
    const float* bl    = (const float*)d_in[6];
    const float* Wr    = (const float*)d_in[7];
    const float* Wp    = (const float*)d_in[8];
    const float* bp    = (const float*)d_in[9];
    const float* Wv    = (const float*)d_in[10];
    const float* bv    = (const float*)d_in[11];
    float* out = (float*)d_out;

    k_detect<<<1, 1>>>(edge);
    k_setup<<<(NN + 255) / 256, 256>>>(batch);            // zeroes d_deg first
    k_convert_edges<<<(2 * NE + 255) / 256, 256>>>(edge); // fused degree count
    k_invdeg<<<(NN + 255) / 256, 256>>>();
    k_scan_a<<<98, 256>>>();
    k_scan_b<<<1, 128>>>();
    k_scan_c<<<(NN + 255) / 256, 256>>>();
    k_scatter<<<(NE + 255) / 256, 256>>>();

    k_encoder<<<(NN * 32 + 255) / 256, 256>>>(x, Wenc, benc);

    int sel = 0;  // current h buffer: 0 -> d_h0
    for (int i = 0; i < NL; i++) {
        k_aggregate<<<(NN * 32 + 255) / 256, 256>>>();
        k_layer<<<(NN + 127) / 128, 128>>>(sel, Wl + i * HD * HD, bl + i * HD,
                                           Wr + i * HD * HD);
        sel ^= 1;
    }

    k_count<<<(NN + 255) / 256, 256>>>();
    k_pool<<<(NN + 255) / 256, 64>>>(sel);
    k_policy<<<(NA + 127) / 128, 128>>>(Wp, bp, out);
    k_value<<<1, 64>>>(Wv, bv, out);
}

// round 3
// speedup vs baseline: 1.1636x; 1.1636x over previous
#include <cuda_runtime.h>
#include <cuda_fp16.h>
#include <math.h>

#define NN 100000
#define NE 3200000
#define FIN 32
#define HD 64
#define NL 4
#define NA 6158
#define NG 64

// ---------------- scratch (device globals; no allocation allowed) -------------
__device__ int   d_flag;              // 1 if inputs are int64, 0 if int32
__device__ int   d_src[NE];
__device__ int   d_dst[NE];
__device__ int   d_batch32[NN];
__device__ int   d_deg[NN];
__device__ int   d_rowptr[NN + 1];
__device__ int   d_cursor[NN];
__device__ int   d_csr[NE];
__device__ float d_invdeg[NN];
__device__ float d_h0[NN * HD];
__device__ float d_h1[NN * HD];
__device__ __half2 d_hh[NN * 32];     // fp16 copy of current h for gathers
__device__ float d_agg[NN * HD];
__device__ float d_gsum[NG * HD];
__device__ int   d_gcnt[NG];
__device__ int   d_part[256];

// ---------------- f32x2 packed-FMA helpers -------------------------------------
__device__ __forceinline__ unsigned long long pack2(float x) {
    unsigned long long r;
    asm("mov.b64 %0, {%1, %1};" : "=l"(r) : "f"(x));
    return r;
}
__device__ __forceinline__ void ffma2(unsigned long long& d,
                                      unsigned long long a,
                                      unsigned long long b) {
    asm("fma.rn.f32x2 %0, %1, %2, %0;" : "+l"(d) : "l"(a), "l"(b));
}
__device__ __forceinline__ void unpack2(unsigned long long v, float& lo, float& hi) {
    asm("mov.b64 {%0, %1}, %2;" : "=f"(lo), "=f"(hi) : "l"(v));
}

// ---------------- dtype detection + conversion --------------------------------
__global__ void k_detect(const void* edge) {
    const unsigned int* w = (const unsigned int*)edge;
    int zeros = 0;
    for (int i = 0; i < 128; i++) if (w[2 * i + 1] == 0u) zeros++;
    d_flag = (zeros >= 120) ? 1 : 0;
}

// converts edges AND accumulates in-degree for dst (fused, saves a 12.8MB pass)
__global__ void k_convert_edges(const void* edge) {
    int i = blockIdx.x * blockDim.x + threadIdx.x;
    if (i >= 2 * NE) return;
    int v;
    if (d_flag) v = (int)((const long long*)edge)[i];
    else        v = ((const int*)edge)[i];
    if (i < NE) d_src[i] = v;
    else        { d_dst[i - NE] = v; atomicAdd(&d_deg[v], 1); }
}

// zero degree + graph accumulators, convert batch ids (runs BEFORE convert)
__global__ void k_setup(const void* batch) {
    int i = blockIdx.x * blockDim.x + threadIdx.x;
    if (i < NN) {
        d_deg[i] = 0;
        int b;
        if (d_flag) b = (int)((const long long*)batch)[i];
        else        b = ((const int*)batch)[i];
        d_batch32[i] = b;
    }
    if (i < NG) d_gcnt[i] = 0;
    if (i < NG * HD) d_gsum[i] = 0.f;
}

__global__ void k_invdeg() {
    int n = blockIdx.x * blockDim.x + threadIdx.x;
    if (n >= NN) return;
    d_invdeg[n] = 1.0f / fmaxf((float)d_deg[n], 1.0f);
}

// ---------------- CSR build (scan over degrees) --------------------------------
__global__ void k_scan_a() {
    __shared__ int ts[256];
    int b = blockIdx.x, t = threadIdx.x;
    int base = b * 1024 + t * 4;
    int v[4];
    int s = 0;
#pragma unroll
    for (int j = 0; j < 4; j++) {
        int idx = base + j;
        v[j] = (idx < NN) ? d_deg[idx] : 0;
        s += v[j];
    }
    ts[t] = s;
    __syncthreads();
    for (int off = 1; off < 256; off <<= 1) {
        int x = (t >= off) ? ts[t - off] : 0;
        __syncthreads();
        ts[t] += x;
        __syncthreads();
    }
    int run = ts[t] - s;
#pragma unroll
    for (int j = 0; j < 4; j++) {
        int idx = base + j;
        if (idx < NN) d_rowptr[idx] = run;
        run += v[j];
    }
    if (t == 255) d_part[b] = ts[255];
}

__global__ void k_scan_b() {
    __shared__ int ps[128];
    int t = threadIdx.x;
    int orig = (t < 98) ? d_part[t] : 0;
    ps[t] = orig;
    __syncthreads();
    for (int off = 1; off < 128; off <<= 1) {
        int x = (t >= off) ? ps[t - off] : 0;
        __syncthreads();
        ps[t] += x;
        __syncthreads();
    }
    d_part[t] = ps[t] - orig;
    if (t == 0) d_rowptr[NN] = NE;
}

__global__ void k_scan_c() {
    int i = blockIdx.x * blockDim.x + threadIdx.x;
    if (i >= NN) return;
    int r = d_rowptr[i] + d_part[i >> 10];
    d_rowptr[i] = r;
    d_cursor[i] = r;
}

__global__ void k_scatter() {
    int e = blockIdx.x * blockDim.x + threadIdx.x;
    if (e >= NE) return;
    int dd = d_dst[e];
    int pos = atomicAdd(&d_cursor[dd], 1);
    d_csr[pos] = d_src[e];
}

// ---------------- encoder: h0 = relu(x @ W_enc^T + b_enc), writes fp32 + fp16 --
__global__ void k_encoder(const float* __restrict__ x,
                          const float* __restrict__ Wenc,
                          const float* __restrict__ benc) {
    __shared__ float Ws[FIN * HD];  // transposed: Ws[k*HD + j]
    __shared__ float bs[HD];
    int t = threadIdx.x;
    for (int i = t; i < HD * FIN; i += blockDim.x) {
        int j = i / FIN, k = i % FIN;
        Ws[k * HD + j] = Wenc[i];
    }
    if (t < HD) bs[t] = benc[t];
    __syncthreads();
    int idx = blockIdx.x * blockDim.x + t;
    if (idx >= NN * 32) return;
    int n = idx >> 5, j2 = idx & 31;
    int j = 2 * j2;
    const float* xr = x + n * FIN;
    float a0 = bs[j], a1 = bs[j + 1];
#pragma unroll
    for (int k = 0; k < FIN; k += 4) {
        float4 xv = *(const float4*)(xr + k);
        float2 w0 = *(const float2*)(&Ws[k * HD + j]);
        float2 w1 = *(const float2*)(&Ws[(k + 1) * HD + j]);
        float2 w2 = *(const float2*)(&Ws[(k + 2) * HD + j]);
        float2 w3 = *(const float2*)(&Ws[(k + 3) * HD + j]);
        a0 += xv.x * w0.x + xv.y * w1.x + xv.z * w2.x + xv.w * w3.x;
        a1 += xv.x * w0.y + xv.y * w1.y + xv.z * w2.y + xv.w * w3.y;
    }
    a0 = fmaxf(a0, 0.f);
    a1 = fmaxf(a1, 0.f);
    ((float2*)d_h0)[idx] = make_float2(a0, a1);
    d_hh[idx] = __floats2half2_rn(a0, a1);
}

// ---------------- coalesced fp32 -> fp16 conversion of current h ---------------
__global__ void k_tohalf(int sel) {
    const float4* __restrict__ h = (const float4*)(sel ? d_h1 : d_h0);
    int i = blockIdx.x * blockDim.x + threadIdx.x;   // one float4 -> two half2
    if (i >= NN * 16) return;
    float4 v = h[i];
    __half2 lo = __floats2half2_rn(v.x, v.y);
    __half2 hi = __floats2half2_rn(v.z, v.w);
    unsigned int ulo = *(unsigned int*)&lo;
    unsigned int uhi = *(unsigned int*)&hi;
    ((uint2*)d_hh)[i] = make_uint2(ulo, uhi);
}

// ---------------- aggregation: agg[n] = mean_{e: dst=n} h_fp16[src[e]] ---------
__global__ void k_aggregate() {
    int w = (blockIdx.x * blockDim.x + threadIdx.x) >> 5;
    if (w >= NN) return;
    int lane = threadIdx.x & 31;
    int beg = d_rowptr[w], end = d_rowptr[w + 1];
    float ax = 0.f, ay = 0.f;
    int i = beg;
    for (; i + 4 <= end; i += 4) {
        int s0 = d_csr[i], s1 = d_csr[i + 1], s2 = d_csr[i + 2], s3 = d_csr[i + 3];
        float2 v0 = __half22float2(d_hh[s0 * 32 + lane]);
        float2 v1 = __half22float2(d_hh[s1 * 32 + lane]);
        float2 v2 = __half22float2(d_hh[s2 * 32 + lane]);
        float2 v3 = __half22float2(d_hh[s3 * 32 + lane]);
        ax += v0.x + v1.x + v2.x + v3.x;
        ay += v0.y + v1.y + v2.y + v3.y;
    }
    for (; i < end; i++) {
        float2 v = __half22float2(d_hh[d_csr[i] * 32 + lane]);
        ax += v.x; ay += v.y;
    }
    float id = d_invdeg[w];
    ((float2*)d_agg)[w * 32 + lane] = make_float2(ax * id, ay * id);
}

// ---------------- layer: h_out = relu(agg@Wl^T + bl + h@Wr^T) + h --------------
// f32x2 packed FMAs; W transposed in smem with pad-68 rows (16B aligned).
#define WPAD 68
__global__ void __launch_bounds__(128)
k_layer(int sel,
        const float* __restrict__ Wl, const float* __restrict__ bl,
        const float* __restrict__ Wr) {
    const float* h    = sel ? d_h1 : d_h0;
    float*       hout = sel ? d_h0 : d_h1;
    __shared__ float Wls[HD * WPAD];  // Wls[k*WPAD + j] = Wl[j][k]
    __shared__ float Wrs[HD * WPAD];
    __shared__ float bls[HD];
    int t = threadIdx.x;
    for (int i = t; i < HD * HD; i += 128) {
        int j = i >> 6, k = i & 63;           // coalesced global read
        Wls[k * WPAD + j] = Wl[i];
        Wrs[k * WPAD + j] = Wr[i];
    }
    if (t < HD) bls[t] = bl[t];
    __syncthreads();
    int n = blockIdx.x * 128 + t;
    if (n >= NN) return;

    unsigned long long acc2[32];
#pragma unroll
    for (int j2 = 0; j2 < 32; j2++)
        acc2[j2] = ((const unsigned long long*)bls)[j2];  // bias pre-packed

    const float4* __restrict__ ar = (const float4*)(d_agg + n * HD);
    const float4* __restrict__ hr = (const float4*)(h + n * HD);
#pragma unroll 2
    for (int k4 = 0; k4 < 16; k4++) {
        float4 a = ar[k4];
        float4 b = hr[k4];
        unsigned long long aa[4] = {pack2(a.x), pack2(a.y), pack2(a.z), pack2(a.w)};
        unsigned long long hh[4] = {pack2(b.x), pack2(b.y), pack2(b.z), pack2(b.w)};
#pragma unroll
        for (int kk = 0; kk < 4; kk++) {
            int k = k4 * 4 + kk;
            const ulonglong2* __restrict__ wl = (const ulonglong2*)&Wls[k * WPAD];
            const ulonglong2* __restrict__ wr = (const ulonglong2*)&Wrs[k * WPAD];
#pragma unroll
            for (int j4 = 0; j4 < 16; j4++) {
                ulonglong2 wlv = wl[j4];
                ulonglong2 wrv = wr[j4];
                ffma2(acc2[2 * j4 + 0], aa[kk], wlv.x);
                ffma2(acc2[2 * j4 + 1], aa[kk], wlv.y);
                ffma2(acc2[2 * j4 + 0], hh[kk], wrv.x);
                ffma2(acc2[2 * j4 + 1], hh[kk], wrv.y);
            }
        }
    }

    const float2* __restrict__ hres = (const float2*)(h + n * HD);
#pragma unroll
    for (int j2 = 0; j2 < 32; j2 += 2) {
        float lo0, hi0, lo1, hi1;
        unpack2(acc2[j2], lo0, hi0);
        unpack2(acc2[j2 + 1], lo1, hi1);
        float2 hv0 = hres[j2];
        float2 hv1 = hres[j2 + 1];
        float4 o;
        o.x = fmaxf(lo0, 0.f) + hv0.x;
        o.y = fmaxf(hi0, 0.f) + hv0.y;
        o.z = fmaxf(lo1, 0.f) + hv1.x;
        o.w = fmaxf(hi1, 0.f) + hv1.y;
        *(float4*)(hout + n * HD + 2 * j2) = o;
    }
}

// ---------------- global mean pool ---------------------------------------------
__global__ void k_count() {
    int n = blockIdx.x * blockDim.x + threadIdx.x;
    if (n >= NN) return;
    atomicAdd(&d_gcnt[d_batch32[n]], 1);
}

__global__ void k_pool(int sel) {
    const float* h = sel ? d_h1 : d_h0;
    int t = threadIdx.x;
    int n0 = blockIdx.x * 256;
    if (n0 >= NN) return;
    int nend = n0 + 256; if (nend > NN) nend = NN;
    int cur = d_batch32[n0];
    float acc = 0.f;
    for (int n = n0; n < nend; n++) {
        int g = d_batch32[n];
        if (g != cur) {
            atomicAdd(&d_gsum[cur * HD + t], acc);
            acc = 0.f;
            cur = g;
        }
        acc += h[n * HD + t];
    }
    atomicAdd(&d_gsum[cur * HD + t], acc);
}

// ---------------- heads --------------------------------------------------------
__global__ void __launch_bounds__(128)
k_policy(const float* __restrict__ Wp, const float* __restrict__ bp,
         float* __restrict__ out) {
    __shared__ float repr[NG * HD];
    int t = threadIdx.x;
    for (int i = t; i < NG * HD; i += 128) {
        int g = i >> 6;
        repr[i] = d_gsum[i] / fmaxf((float)d_gcnt[g], 1.f);
    }
    __syncthreads();
    int a = blockIdx.x * 128 + t;
    if (a >= NA) return;
    float acc[NG];
#pragma unroll
    for (int g = 0; g < NG; g++) acc[g] = 0.f;
    const float4* __restrict__ wr = (const float4*)(Wp + a * HD);
#pragma unroll 2
    for (int k4 = 0; k4 < 16; k4++) {
        float4 w = wr[k4];
#pragma unroll
        for (int g = 0; g < NG; g++) {
            float4 r = *(const float4*)(&repr[g * HD + k4 * 4]);
            acc[g] += w.x * r.x + w.y * r.y + w.z * r.z + w.w * r.w;
        }
    }
    float bias = bp[a];
#pragma unroll
    for (int g = 0; g < NG; g++) out[g * NA + a] = acc[g] + bias;
}

__global__ void k_value(const float* __restrict__ Wv,
                        const float* __restrict__ bv,
                        float* __restrict__ out) {
    int g = threadIdx.x;
    if (g >= NG) return;
    float inv = 1.f / fmaxf((float)d_gcnt[g], 1.f);
    float acc = 0.f;
#pragma unroll
    for (int k = 0; k < HD; k++) acc += d_gsum[g * HD + k] * Wv[k];
    out[NG * NA + g] = tanhf(acc * inv + bv[0]);
}

// ---------------- launcher -----------------------------------------------------
extern "C" void kernel_launch(void* const* d_in, const int* in_sizes, int n_in,
                              void* d_out, int out_size) {
    const float* x     = (const float*)d_in[0];
    const void*  edge  = d_in[1];
    const void*  batch = d_in[2];
    const float* Wenc  = (const float*)d_in[3];
    const float* benc  = (const float*)d_in[4];
    const float* Wl    = (const float*)d_in[5];
    const float* bl    = (const float*)d_in[6];
    const float* Wr    = (const float*)d_in[7];
    const float* Wp    = (const float*)d_in[8];
    const float* bp    = (const float*)d_in[9];
    const float* Wv    = (const float*)d_in[10];
    const float* bv    = (const float*)d_in[11];
    float* out = (float*)d_out;

    k_detect<<<1, 1>>>(edge);
    k_setup<<<(NN + 255) / 256, 256>>>(batch);            // zeroes d_deg first
    k_convert_edges<<<(2 * NE + 255) / 256, 256>>>(edge); // fused degree count
    k_invdeg<<<(NN + 255) / 256, 256>>>();
    k_scan_a<<<98, 256>>>();
    k_scan_b<<<1, 128>>>();
    k_scan_c<<<(NN + 255) / 256, 256>>>();
    k_scatter<<<(NE + 255) / 256, 256>>>();

    k_encoder<<<(NN * 32 + 255) / 256, 256>>>(x, Wenc, benc);

    int sel = 0;  // current h buffer: 0 -> d_h0
    for (int i = 0; i < NL; i++) {
        k_aggregate<<<(NN * 32 + 255) / 256, 256>>>();
        k_layer<<<(NN + 127) / 128, 128>>>(sel, Wl + i * HD * HD, bl + i * HD,
                                           Wr + i * HD * HD);
        sel ^= 1;
        if (i < NL - 1)
            k_tohalf<<<(NN * 16 + 255) / 256, 256>>>(sel);
    }

    k_count<<<(NN + 255) / 256, 256>>>();
    k_pool<<<(NN + 255) / 256, 64>>>(sel);
    k_policy<<<(NA + 127) / 128, 128>>>(Wp, bp, out);
    k_value<<<1, 64>>>(Wv, bv, out);
}

// round 4
// speedup vs baseline: 1.3907x; 1.1952x over previous
#include <cuda_runtime.h>
#include <cuda_fp16.h>
#include <math.h>

#define NN 100000
#define NE 3200000
#define FIN 32
#define HD 64
#define NL 4
#define NA 6158
#define NG 64
#define WPAD 68

// ---------------- scratch (device globals; no allocation allowed) -------------
__device__ int   d_flag;
__device__ int   d_src[NE];
__device__ int   d_dst[NE];
__device__ int   d_batch32[NN];
__device__ int   d_deg[NN];
__device__ int   d_rowptr[NN + 1];
__device__ int   d_cursor[NN];
__device__ int   d_csr[NE];
__device__ float d_invdeg[NN];
__device__ float d_h0[NN * HD];
__device__ float d_h1[NN * HD];
__device__ __half2 d_hh[NN * 32];
__device__ float d_agg[NN * HD];
__device__ float d_gsum[NG * HD];
__device__ int   d_gcnt[NG];
__device__ int   d_part[256];

// ---------------- f32x2 packed-FMA helpers -------------------------------------
__device__ __forceinline__ unsigned long long pack2(float x) {
    unsigned long long r;
    asm("mov.b64 %0, {%1, %1};" : "=l"(r) : "f"(x));
    return r;
}
__device__ __forceinline__ void ffma2(unsigned long long& d,
                                      unsigned long long a,
                                      unsigned long long b) {
    asm("fma.rn.f32x2 %0, %1, %2, %0;" : "+l"(d) : "l"(a), "l"(b));
}
__device__ __forceinline__ void unpack2(unsigned long long v, float& lo, float& hi) {
    asm("mov.b64 {%0, %1}, %2;" : "=f"(lo), "=f"(hi) : "l"(v));
}

// ---------------- encoder: h0 = relu(x @ W_enc^T + b_enc) (independent, idx 0) -
__global__ void k_encoder(const float* __restrict__ x,
                          const float* __restrict__ Wenc,
                          const float* __restrict__ benc) {
    __shared__ float Ws[FIN * HD];
    __shared__ float bs[HD];
    int t = threadIdx.x;
    for (int i = t; i < HD * FIN; i += blockDim.x) {
        int j = i / FIN, k = i % FIN;
        Ws[k * HD + j] = Wenc[i];
    }
    if (t < HD) bs[t] = benc[t];
    __syncthreads();
    int idx = blockIdx.x * blockDim.x + t;
    if (idx >= NN * 32) return;
    int n = idx >> 5, j2 = idx & 31;
    int j = 2 * j2;
    const float* xr = x + n * FIN;
    float a0 = bs[j], a1 = bs[j + 1];
#pragma unroll
    for (int k = 0; k < FIN; k += 4) {
        float4 xv = *(const float4*)(xr + k);
        float2 w0 = *(const float2*)(&Ws[k * HD + j]);
        float2 w1 = *(const float2*)(&Ws[(k + 1) * HD + j]);
        float2 w2 = *(const float2*)(&Ws[(k + 2) * HD + j]);
        float2 w3 = *(const float2*)(&Ws[(k + 3) * HD + j]);
        a0 += xv.x * w0.x + xv.y * w1.x + xv.z * w2.x + xv.w * w3.x;
        a1 += xv.x * w0.y + xv.y * w1.y + xv.z * w2.y + xv.w * w3.y;
    }
    a0 = fmaxf(a0, 0.f);
    a1 = fmaxf(a1, 0.f);
    ((float2*)d_h0)[idx] = make_float2(a0, a1);
    d_hh[idx] = __floats2half2_rn(a0, a1);
}

// ---------------- detect dtype + zero accumulators ------------------------------
__global__ void k_detect(const void* edge) {
    int i = blockIdx.x * blockDim.x + threadIdx.x;
    if (i == 0) {
        const unsigned int* w = (const unsigned int*)edge;
        int zeros = 0;
        for (int j = 0; j < 128; j++) if (w[2 * j + 1] == 0u) zeros++;
        d_flag = (zeros >= 120) ? 1 : 0;
    }
    if (i < NN) d_deg[i] = 0;
    if (i < NG) d_gcnt[i] = 0;
    if (i < NG * HD) d_gsum[i] = 0.f;
}

// converts edges AND accumulates in-degree for dst (fused)
__global__ void k_convert_edges(const void* edge) {
    int i = blockIdx.x * blockDim.x + threadIdx.x;
    if (i >= 2 * NE) return;
    int v;
    if (d_flag) v = (int)((const long long*)edge)[i];
    else        v = ((const int*)edge)[i];
    if (i < NE) d_src[i] = v;
    else        { d_dst[i - NE] = v; atomicAdd(&d_deg[v], 1); }
}

// ---------------- CSR build (scan over degrees) --------------------------------
__global__ void k_scan_a() {
    __shared__ int ts[256];
    int b = blockIdx.x, t = threadIdx.x;
    int base = b * 1024 + t * 4;
    int v[4];
    int s = 0;
#pragma unroll
    for (int j = 0; j < 4; j++) {
        int idx = base + j;
        v[j] = (idx < NN) ? d_deg[idx] : 0;
        s += v[j];
    }
    ts[t] = s;
    __syncthreads();
    for (int off = 1; off < 256; off <<= 1) {
        int x = (t >= off) ? ts[t - off] : 0;
        __syncthreads();
        ts[t] += x;
        __syncthreads();
    }
    int run = ts[t] - s;
#pragma unroll
    for (int j = 0; j < 4; j++) {
        int idx = base + j;
        if (idx < NN) d_rowptr[idx] = run;
        run += v[j];
    }
    if (t == 255) d_part[b] = ts[255];
}

__global__ void k_scan_b() {
    __shared__ int ps[128];
    int t = threadIdx.x;
    int orig = (t < 98) ? d_part[t] : 0;
    ps[t] = orig;
    __syncthreads();
    for (int off = 1; off < 128; off <<= 1) {
        int x = (t >= off) ? ps[t - off] : 0;
        __syncthreads();
        ps[t] += x;
        __syncthreads();
    }
    d_part[t] = ps[t] - orig;
    if (t == 0) d_rowptr[NN] = NE;
}

// scan finalize + invdeg + batch conversion + graph counts (fused)
__global__ void k_scan_c(const void* batch) {
    int i = blockIdx.x * blockDim.x + threadIdx.x;
    if (i >= NN) return;
    int r = d_rowptr[i] + d_part[i >> 10];
    d_rowptr[i] = r;
    d_cursor[i] = r;
    d_invdeg[i] = 1.0f / fmaxf((float)d_deg[i], 1.0f);
    int b;
    if (d_flag) b = (int)((const long long*)batch)[i];
    else        b = ((const int*)batch)[i];
    d_batch32[i] = b;
    atomicAdd(&d_gcnt[b], 1);
}

__global__ void k_scatter() {
    int e = blockIdx.x * blockDim.x + threadIdx.x;
    if (e >= NE) return;
    int dd = d_dst[e];
    int pos = atomicAdd(&d_cursor[dd], 1);
    d_csr[pos] = d_src[e];
}

// ---------------- aggregation: agg[n] = mean_{e: dst=n} h_fp16[src[e]] ---------
// unroll 8, dual accumulators -> MLP 8 against ~250cyc L2 gather latency
__global__ void k_aggregate() {
    int w = (blockIdx.x * blockDim.x + threadIdx.x) >> 5;
    if (w >= NN) return;
    int lane = threadIdx.x & 31;
    int beg = d_rowptr[w], end = d_rowptr[w + 1];
    const __half2* __restrict__ hp = d_hh;
    float ax0 = 0.f, ay0 = 0.f, ax1 = 0.f, ay1 = 0.f;
    int i = beg;
    for (; i + 8 <= end; i += 8) {
        int s0 = d_csr[i + 0], s1 = d_csr[i + 1], s2 = d_csr[i + 2], s3 = d_csr[i + 3];
        int s4 = d_csr[i + 4], s5 = d_csr[i + 5], s6 = d_csr[i + 6], s7 = d_csr[i + 7];
        float2 v0 = __half22float2(hp[s0 * 32 + lane]);
        float2 v1 = __half22float2(hp[s1 * 32 + lane]);
        float2 v2 = __half22float2(hp[s2 * 32 + lane]);
        float2 v3 = __half22float2(hp[s3 * 32 + lane]);
        float2 v4 = __half22float2(hp[s4 * 32 + lane]);
        float2 v5 = __half22float2(hp[s5 * 32 + lane]);
        float2 v6 = __half22float2(hp[s6 * 32 + lane]);
        float2 v7 = __half22float2(hp[s7 * 32 + lane]);
        ax0 += v0.x + v1.x + v2.x + v3.x;
        ay0 += v0.y + v1.y + v2.y + v3.y;
        ax1 += v4.x + v5.x + v6.x + v7.x;
        ay1 += v4.y + v5.y + v6.y + v7.y;
    }
    for (; i < end; i++) {
        float2 v = __half22float2(hp[d_csr[i] * 32 + lane]);
        ax0 += v.x; ay0 += v.y;
    }
    float id = d_invdeg[w];
    ((float2*)d_agg)[w * 32 + lane] = make_float2((ax0 + ax1) * id, (ay0 + ay1) * id);
}

// ---------------- layer: h_out = relu(agg@Wl^T + bl + h@Wr^T) + h --------------
// v2: 2 nodes/thread, j-half split across thread pairs -> LDS:FFMA2 = 1:4.
// smem-staged coalesced stores for hout (fp32) + d_hh (fp16, fused tohalf).
__global__ void __launch_bounds__(256, 2)
k_layer(int sel,
        const float* __restrict__ Wl, const float* __restrict__ bl,
        const float* __restrict__ Wr) {
    const float* h    = sel ? d_h1 : d_h0;
    float*       hout = sel ? d_h0 : d_h1;
    __shared__ float S[2 * HD * WPAD + HD];   // Wls | Wrs | bls ; stage reuses [0, 8704)
    float* Wls = S;
    float* Wrs = S + HD * WPAD;
    float* bls = S + 2 * HD * WPAD;
    int t = threadIdx.x;
    for (int i = t; i < HD * HD; i += 256) {
        int j = i >> 6, k = i & 63;
        Wls[k * WPAD + j] = Wl[i];
        Wrs[k * WPAD + j] = Wr[i];
    }
    if (t < HD) bls[t] = bl[t];
    __syncthreads();

    int p    = t & 127;   // pair id -> nodes 2p, 2p+1
    int jh   = t >> 7;    // j-half: outputs [32*jh, 32*jh+32)
    int base = blockIdx.x * 256;
    int n0 = base + 2 * p, n1 = n0 + 1;
    bool v0 = (n0 < NN), v1 = (n1 < NN);

    unsigned long long accA[16], accB[16];
    {
        const unsigned long long* bp2 = (const unsigned long long*)(bls + jh * 32);
#pragma unroll
        for (int q = 0; q < 16; q++) { accA[q] = bp2[q]; accB[q] = bp2[q]; }
    }

    float oA[32], oB[32];
    if (v0) {
        const float4* __restrict__ arA = (const float4*)(d_agg + n0 * HD);
        const float4* __restrict__ hrA = (const float4*)(h + n0 * HD);
        const float4* __restrict__ arB = (const float4*)(d_agg + n1 * HD);
        const float4* __restrict__ hrB = (const float4*)(h + n1 * HD);
#pragma unroll 2
        for (int k4 = 0; k4 < 16; k4++) {
            float4 aA = arA[k4], hA = hrA[k4];
            float4 aB, hB;
            if (v1) { aB = arB[k4]; hB = hrB[k4]; }
            else    { aB = make_float4(0, 0, 0, 0); hB = aB; }
            float aAv[4] = {aA.x, aA.y, aA.z, aA.w};
            float hAv[4] = {hA.x, hA.y, hA.z, hA.w};
            float aBv[4] = {aB.x, aB.y, aB.z, aB.w};
            float hBv[4] = {hB.x, hB.y, hB.z, hB.w};
#pragma unroll
            for (int kk = 0; kk < 4; kk++) {
                int k = k4 * 4 + kk;
                const ulonglong2* __restrict__ wl =
                    (const ulonglong2*)(Wls + k * WPAD + jh * 32);
                const ulonglong2* __restrict__ wr =
                    (const ulonglong2*)(Wrs + k * WPAD + jh * 32);
                unsigned long long aAp = pack2(aAv[kk]);
                unsigned long long hAp = pack2(hAv[kk]);
                unsigned long long aBp = pack2(aBv[kk]);
                unsigned long long hBp = pack2(hBv[kk]);
#pragma unroll
                for (int j4 = 0; j4 < 8; j4++) {
                    ulonglong2 L = wl[j4];
                    ulonglong2 R = wr[j4];
                    ffma2(accA[2 * j4 + 0], aAp, L.x);
                    ffma2(accA[2 * j4 + 1], aAp, L.y);
                    ffma2(accA[2 * j4 + 0], hAp, R.x);
                    ffma2(accA[2 * j4 + 1], hAp, R.y);
                    ffma2(accB[2 * j4 + 0], aBp, L.x);
                    ffma2(accB[2 * j4 + 1], aBp, L.y);
                    ffma2(accB[2 * j4 + 0], hBp, R.x);
                    ffma2(accB[2 * j4 + 1], hBp, R.y);
                }
            }
        }
        // epilogue: relu + residual
#pragma unroll
        for (int q = 0; q < 16; q++) {
            unpack2(accA[q], oA[2 * q], oA[2 * q + 1]);
            unpack2(accB[q], oB[2 * q], oB[2 * q + 1]);
        }
        const float4* __restrict__ resA = (const float4*)(h + n0 * HD + jh * 32);
#pragma unroll
        for (int f = 0; f < 8; f++) {
            float4 r = resA[f];
            oA[4 * f + 0] = fmaxf(oA[4 * f + 0], 0.f) + r.x;
            oA[4 * f + 1] = fmaxf(oA[4 * f + 1], 0.f) + r.y;
            oA[4 * f + 2] = fmaxf(oA[4 * f + 2], 0.f) + r.z;
            oA[4 * f + 3] = fmaxf(oA[4 * f + 3], 0.f) + r.w;
        }
        if (v1) {
            const float4* __restrict__ resB = (const float4*)(h + n1 * HD + jh * 32);
#pragma unroll
            for (int f = 0; f < 8; f++) {
                float4 r = resB[f];
                oB[4 * f + 0] = fmaxf(oB[4 * f + 0], 0.f) + r.x;
                oB[4 * f + 1] = fmaxf(oB[4 * f + 1], 0.f) + r.y;
                oB[4 * f + 2] = fmaxf(oB[4 * f + 2], 0.f) + r.z;
                oB[4 * f + 3] = fmaxf(oB[4 * f + 3], 0.f) + r.w;
            }
        }
    }

    // staged, coalesced output: 2 waves of 128 nodes each (stage reuses W smem)
    float* stage = S;   // 128 rows x 68 floats = 8704 floats
#pragma unroll
    for (int wv = 0; wv < 2; wv++) {
        __syncthreads();   // wave0: W reads done; wave1: stage reads done
        if ((p >> 6) == wv && v0) {
            int ln = 2 * (p & 63);
            float4* sA = (float4*)(stage + ln * WPAD + jh * 32);
#pragma unroll
            for (int f = 0; f < 8; f++)
                sA[f] = make_float4(oA[4 * f], oA[4 * f + 1], oA[4 * f + 2], oA[4 * f + 3]);
            if (v1) {
                float4* sB = (float4*)(stage + (ln + 1) * WPAD + jh * 32);
#pragma unroll
                for (int f = 0; f < 8; f++)
                    sB[f] = make_float4(oB[4 * f], oB[4 * f + 1], oB[4 * f + 2], oB[4 * f + 3]);
            }
        }
        __syncthreads();
        // 128 nodes x 16 float4 = 2048 float4, 256 threads -> 8 iters, coalesced
        for (int i2 = t; i2 < 2048; i2 += 256) {
            int node = i2 >> 4, f = i2 & 15;
            int gn = base + wv * 128 + node;
            if (gn < NN) {
                float4 vv = *(const float4*)(stage + node * WPAD + f * 4);
                *(float4*)(hout + gn * 64 + f * 4) = vv;
                __half2 l2 = __floats2half2_rn(vv.x, vv.y);
                __half2 h2 = __floats2half2_rn(vv.z, vv.w);
                unsigned int ul = *(unsigned int*)&l2;
                unsigned int uh = *(unsigned int*)&h2;
                ((uint2*)d_hh)[gn * 16 + f] = make_uint2(ul, uh);
            }
        }
    }
}

// ---------------- global mean pool ---------------------------------------------
__global__ void k_pool(int sel) {
    const float* h = sel ? d_h1 : d_h0;
    int t = threadIdx.x;
    int n0 = blockIdx.x * 256;
    if (n0 >= NN) return;
    int nend = n0 + 256; if (nend > NN) nend = NN;
    int cur = d_batch32[n0];
    float acc = 0.f;
    for (int n = n0; n < nend; n++) {
        int g = d_batch32[n];
        if (g != cur) {
            atomicAdd(&d_gsum[cur * HD + t], acc);
            acc = 0.f;
            cur = g;
        }
        acc += h[n * HD + t];
    }
    atomicAdd(&d_gsum[cur * HD + t], acc);
}

// ---------------- heads --------------------------------------------------------
__global__ void __launch_bounds__(128)
k_policy(const float* __restrict__ Wp, const float* __restrict__ bp,
         float* __restrict__ out) {
    __shared__ float repr[NG * HD];
    int t = threadIdx.x;
    for (int i = t; i < NG * HD; i += 128) {
        int g = i >> 6;
        repr[i] = d_gsum[i] / fmaxf((float)d_gcnt[g], 1.f);
    }
    __syncthreads();
    int a = blockIdx.x * 128 + t;
    if (a >= NA) return;
    float acc[NG];
#pragma unroll
    for (int g = 0; g < NG; g++) acc[g] = 0.f;
    const float4* __restrict__ wr = (const float4*)(Wp + a * HD);
#pragma unroll 2
    for (int k4 = 0; k4 < 16; k4++) {
        float4 w = wr[k4];
#pragma unroll
        for (int g = 0; g < NG; g++) {
            float4 r = *(const float4*)(&repr[g * HD + k4 * 4]);
            acc[g] += w.x * r.x + w.y * r.y + w.z * r.z + w.w * r.w;
        }
    }
    float bias = bp[a];
#pragma unroll
    for (int g = 0; g < NG; g++) out[g * NA + a] = acc[g] + bias;
}

__global__ void k_value(const float* __restrict__ Wv,
                        const float* __restrict__ bv,
                        float* __restrict__ out) {
    int g = threadIdx.x;
    if (g >= NG) return;
    float inv = 1.f / fmaxf((float)d_gcnt[g], 1.f);
    float acc = 0.f;
#pragma unroll
    for (int k = 0; k < HD; k++) acc += d_gsum[g * HD + k] * Wv[k];
    out[NG * NA + g] = tanhf(acc * inv + bv[0]);
}

// ---------------- launcher -----------------------------------------------------
extern "C" void kernel_launch(void* const* d_in, const int* in_sizes, int n_in,
                              void* d_out, int out_size) {
    const float* x     = (const float*)d_in[0];
    const void*  edge  = d_in[1];
    const void*  batch = d_in[2];
    const float* Wenc  = (const float*)d_in[3];
    const float* benc  = (const float*)d_in[4];
    const float* Wl    = (const float*)d_in[5];
    const float* bl    = (const float*)d_in[6];
    const float* Wr    = (const float*)d_in[7];
    const float* Wp    = (const float*)d_in[8];
    const float* bp    = (const float*)d_in[9];
    const float* Wv    = (const float*)d_in[10];
    const float* bv    = (const float*)d_in[11];
    float* out = (float*)d_out;

    k_encoder<<<(NN * 32 + 255) / 256, 256>>>(x, Wenc, benc);
    k_detect<<<(NN + 255) / 256, 256>>>(edge);
    k_convert_edges<<<(2 * NE + 255) / 256, 256>>>(edge);
    k_scan_a<<<98, 256>>>();
    k_scan_b<<<1, 128>>>();
    k_scan_c<<<(NN + 255) / 256, 256>>>(batch);
    k_scatter<<<(NE + 255) / 256, 256>>>();

    int sel = 0;
    for (int i = 0; i < NL; i++) {
        k_aggregate<<<(NN * 32 + 255) / 256, 256>>>();
        k_layer<<<(NN + 255) / 256, 256>>>(sel, Wl + i * HD * HD, bl + i * HD,
                                           Wr + i * HD * HD);
        sel ^= 1;
    }

    k_pool<<<(NN + 255) / 256, 64>>>(sel);
    k_policy<<<(NA + 127) / 128, 128>>>(Wp, bp, out);
    k_value<<<1, 64>>>(Wv, bv, out);
}